// round 7
// baseline (speedup 1.0000x reference)
#include <cuda_runtime.h>

// Shapes fixed by the dataset
#define CC  64      // classes
#define AA  256     // feature dim
#define CSPLIT 4    // c-slices per y  -> grid 4*64 = 256 blocks
#define CB  16      // classes per block
#define NT  256     // threads per block (8 warps)
#define TR  8       // a-rows per G tile
#define NB  (CSPLIT * CC)   // 256 blocks
#define NROW 4096

// Fixed-slot scratch (deterministic, no allocation)
__device__ float g_S[CC * CC];            // S[y][c]
__device__ float g_blockSums[NB];
__device__ unsigned g_sync  = 0;          // epoch grid-sync counter (monotonic)
__device__ unsigned g_done  = 0;          // epoch final-reduction counter
__device__ int   g_lab64;

// ---------------------------------------------------------------------------
// Single fused kernel:
//   Phase 1: S[y,c] = (w_c - w_y)^T G_y (w_c - w_y)
//     Block (q,y): 16 c's. Warp w: c-group (w&3)*4, b-half (w>>2)*128.
//     Thread: 4c x 4b accumulators; G_y streamed via double-buffered smem tile.
//   epoch grid-sync (all 256 blocks co-resident: 2/SM, 32KB smem, 256 thr)
//   Phase 2: softmax-CE over 16 rows per block + fence-counter final mean
// ---------------------------------------------------------------------------
__global__ __launch_bounds__(NT) void k_fused(
        const float* __restrict__ W, const float* __restrict__ CV,
        const float* __restrict__ pred, const void* __restrict__ labels,
        const float* __restrict__ Lam, float* __restrict__ out) {
    __shared__ float Dq[CB][AA];       // 16 KB
    __shared__ float Gt[2][TR * AA];   // 16 KB double buffer
    __shared__ float ws2[32];          // phase-1 cross-warp combine
    __shared__ float ws[8];            // phase-2 per-warp sums
    __shared__ unsigned s_flag;

    const int y    = blockIdx.y;
    const int q    = blockIdx.x;
    const int tid  = threadIdx.x;
    const int w    = tid >> 5;
    const int lane = tid & 31;
    const int bid  = y * CSPLIT + q;

    // Labels may be int32 (JAX default) or int64 (x64). Range-check the first
    // 8 int64 interpretations: int32 data aliases high words, blows the range.
    if (bid == 0 && tid == 0) {
        int ok = 1;
#pragma unroll
        for (int i = 0; i < 8; i++) {
            long long v = ((const long long*)labels)[i];
            if (v < 0 || v >= CC) ok = 0;
        }
        g_lab64 = ok;
    }

    // ---- Phase 1: quadratic forms -------------------------------------
    // Build Dq = W[q*16 + r][:] - W[y][:]
    const float* wy = W + y * AA;
    for (int idx = tid; idx < CB * (AA / 4); idx += NT) {
        const int r  = idx >> 6;           // / (AA/4)
        const int a4 = (idx & 63) << 2;
        float4 wv = *(const float4*)(W + (q * CB + r) * AA + a4);
        float4 yv = *(const float4*)(wy + a4);
        float4 d;
        d.x = wv.x - yv.x; d.y = wv.y - yv.y;
        d.z = wv.z - yv.z; d.w = wv.w - yv.w;
        *(float4*)(&Dq[r][a4]) = d;
    }

    const float* G = CV + (size_t)y * (AA * AA);

    // Prologue: tile 0 -> buffer 0 (2048 floats; 2 float4 per thread)
    float4 pf0, pf1;
    pf0 = *(const float4*)(G + (0 * NT + tid) * 4);
    pf1 = *(const float4*)(G + (1 * NT + tid) * 4);
    *(float4*)(&Gt[0][(0 * NT + tid) * 4]) = pf0;
    *(float4*)(&Gt[0][(1 * NT + tid) * 4]) = pf1;
    __syncthreads();

    const int cg   = (w & 3) * 4;            // c-group base
    const int bcol = (w >> 2) * 128 + lane * 4;  // this thread's 4 b-cols

    float acc[4][4];
#pragma unroll
    for (int ci = 0; ci < 4; ci++)
#pragma unroll
        for (int k = 0; k < 4; k++) acc[ci][k] = 0.f;

#pragma unroll 1
    for (int t = 0; t < AA / TR; t++) {
        if (t + 1 < AA / TR) {        // prefetch next tile to registers
            const float* Gn = G + (size_t)(t + 1) * (TR * AA);
            pf0 = *(const float4*)(Gn + (0 * NT + tid) * 4);
            pf1 = *(const float4*)(Gn + (1 * NT + tid) * 4);
        }
        const float* buf = Gt[t & 1];
        const int abase = t * TR;
#pragma unroll
        for (int rr = 0; rr < TR; rr += 4) {
            float4 u[4];
#pragma unroll
            for (int ci = 0; ci < 4; ci++)     // warp-broadcast loads
                u[ci] = *(const float4*)(&Dq[cg + ci][abase + rr]);
#pragma unroll
            for (int e = 0; e < 4; e++) {
                float4 g = *(const float4*)(buf + (rr + e) * AA + bcol);
#pragma unroll
                for (int ci = 0; ci < 4; ci++) {
                    const float uu = (e == 0) ? u[ci].x :
                                     (e == 1) ? u[ci].y :
                                     (e == 2) ? u[ci].z : u[ci].w;
                    acc[ci][0] = fmaf(uu, g.x, acc[ci][0]);
                    acc[ci][1] = fmaf(uu, g.y, acc[ci][1]);
                    acc[ci][2] = fmaf(uu, g.z, acc[ci][2]);
                    acc[ci][3] = fmaf(uu, g.w, acc[ci][3]);
                }
            }
        }
        if (t + 1 < AA / TR) {
            __syncthreads();   // all readers done with the buffer we overwrite
            float* nbuf = Gt[(t + 1) & 1];
            *(float4*)(&nbuf[(0 * NT + tid) * 4]) = pf0;
            *(float4*)(&nbuf[(1 * NT + tid) * 4]) = pf1;
            __syncthreads();
        }
    }

    // Epilogue: half-S = sum_b t[c,b]*D[c,b] over this warp's b-half
#pragma unroll
    for (int ci = 0; ci < 4; ci++) {
        float4 d = *(const float4*)(&Dq[cg + ci][bcol]);
        float p = acc[ci][0] * d.x + acc[ci][1] * d.y
                + acc[ci][2] * d.z + acc[ci][3] * d.w;
#pragma unroll
        for (int off = 16; off; off >>= 1)
            p += __shfl_xor_sync(0xffffffffu, p, off);
        if (lane == 0) ws2[w * 4 + ci] = p;
    }
    __syncthreads();
    if (tid < 16) {    // combine the two b-halves (warps wg and wg+4)
        const int wg = tid >> 2, ci = tid & 3;
        g_S[y * CC + q * CB + wg * 4 + ci] =
            ws2[wg * 4 + ci] + ws2[(wg + 4) * 4 + ci];
    }

    // ---- Epoch grid-sync (monotonic counter; graph-replay safe).
    // All 256 blocks co-resident (2/SM easily), so polling cannot deadlock.
    __syncthreads();
    if (tid == 0) {
        __threadfence();
        unsigned old = atomicAdd(&g_sync, 1u);
        unsigned target = (old / NB + 1u) * NB;
        while (*(volatile unsigned*)&g_sync < target) { }
        __threadfence();
    }
    __syncthreads();

    // ---- Phase 2: softmax-CE over rows [bid*16, bid*16+16) -------------
    const int   lab64 = g_lab64;
    const float lam   = 0.5f * __ldg(Lam);

    float wsum = 0.f;
#pragma unroll
    for (int rr = 0; rr < 2; rr++) {
        const int n = bid * 16 + w * 2 + rr;
        const int yl = lab64 ? (int)((const long long*)labels)[n]
                             : ((const int*)labels)[n];
        const float* p = pred + (size_t)n * CC;
        const int c2 = lane + 32;

        float a1 = p[lane] + lam * g_S[yl * CC + lane];
        float a2 = p[c2]   + lam * g_S[yl * CC + c2];

        float m = fmaxf(a1, a2);
#pragma unroll
        for (int off = 16; off; off >>= 1)
            m = fmaxf(m, __shfl_xor_sync(0xffffffffu, m, off));
        float e = __expf(a1 - m) + __expf(a2 - m);
#pragma unroll
        for (int off = 16; off; off >>= 1)
            e += __shfl_xor_sync(0xffffffffu, e, off);
        // y is warp-uniform: fetch a_y with a single shuffle, no reduction
        float ay = __shfl_sync(0xffffffffu, (yl < 32) ? a1 : a2, yl & 31);
        wsum += m + __logf(e) - ay;
    }

    if (lane == 0) ws[w] = wsum;
    __syncthreads();
    if (tid == 0) {
        float s = 0.f;
#pragma unroll
        for (int i = 0; i < 8; i++) s += ws[i];
        g_blockSums[bid] = s;
        __threadfence();
        unsigned old = atomicAdd(&g_done, 1u);
        s_flag = ((old % NB) == NB - 1u) ? 1u : 0u;
    }
    __syncthreads();

    // Last-arriving block: deterministic fixed-order sum of 256 partials
    if (s_flag && w == 0) {
        __threadfence();
        float v = 0.f;
#pragma unroll
        for (int k = 0; k < NB / 32; k++)
            v += g_blockSums[k * 32 + lane];
#pragma unroll
        for (int off = 16; off; off >>= 1)
            v += __shfl_xor_sync(0xffffffffu, v, off);
        if (lane == 0)
            out[0] = v / (float)NROW;
    }
}

// ---------------------------------------------------------------------------
// Inputs (metadata order): fc_weight[C,A] f32, features (unused), pred[N,C] f32,
// labels[N] i32/i64, Lambda[1] f32, covariance_sample[C,A,A] f32.
// ---------------------------------------------------------------------------
extern "C" void kernel_launch(void* const* d_in, const int* in_sizes, int n_in,
                              void* d_out, int out_size) {
    const float* W      = (const float*)d_in[0];
    const float* pred   = (const float*)d_in[2];
    const void*  labels = d_in[3];
    const float* Lam    = (const float*)d_in[4];
    const float* CV     = (const float*)d_in[5];

    k_fused<<<dim3(CSPLIT, CC), NT>>>(W, CV, pred, labels, Lam, (float*)d_out);
}